// round 12
// baseline (speedup 1.0000x reference)
#include <cuda_runtime.h>
#include <math.h>
#include <stdint.h>

// Problem constants (fixed by setup_inputs)
#define BB      4        // b*v
#define HW      4096
#define CC      128
#define DD      64
#define HIDN    256
#define HH      64
#define WW      64
#define ROWS    (BB*HW)  // 16384

__device__ float g_xt [ROWS*CC];
__device__ float g_xn [ROWS*CC];
__device__ float g_q  [ROWS*CC];
__device__ float g_k  [ROWS*CC];
__device__ float g_v  [ROWS*CC];
__device__ float g_ao [ROWS*CC];
__device__ float g_x2 [ROWS*CC];
__device__ float g_xn2[ROWS*CC];
__device__ float g_y  [ROWS*HIDN];
__device__ float g_yt [ROWS*HIDN];

__device__ __forceinline__ float warp_sum(float v) {
    #pragma unroll
    for (int o = 16; o > 0; o >>= 1) v += __shfl_xor_sync(0xffffffffu, v, o);
    return v;
}
__device__ __forceinline__ float warp_max(float v) {
    #pragma unroll
    for (int o = 16; o > 0; o >>= 1) v = fmaxf(v, __shfl_xor_sync(0xffffffffu, v, o));
    return v;
}
__device__ __forceinline__ float gelu_f(float x) {
    return 0.5f * x * (1.0f + erff(x * 0.7071067811865475f));
}

// ---------------------------------------------------------------------------
// Kernel 1: transpose (B,C,HW)->(B,HW,C) + LayerNorm1.  Writes x_t and xn.
// ---------------------------------------------------------------------------
__global__ __launch_bounds__(256)
void transpose_ln1_kernel(const float* __restrict__ feat,
                          const float* __restrict__ g, const float* __restrict__ b,
                          float* __restrict__ xt, float* __restrict__ xn)
{
    __shared__ float tile[32][129];
    const int n  = blockIdx.y;
    const int i0 = blockIdx.x * 32;
    const int tid = threadIdx.x, lane = tid & 31, wp = tid >> 5;

    const float* fptr = feat + (size_t)n * CC * HW;
    #pragma unroll
    for (int c = wp; c < CC; c += 8)
        tile[lane][c] = fptr[(size_t)c * HW + i0 + lane];
    __syncthreads();

    #pragma unroll
    for (int qq = 0; qq < 4; ++qq) {
        const int r = wp * 4 + qq;
        float s = 0.f, sq = 0.f;
        #pragma unroll
        for (int t = 0; t < 4; ++t) { float v = tile[r][lane + t*32]; s += v; sq += v*v; }
        s  = warp_sum(s);
        sq = warp_sum(sq);
        const float m   = s * (1.0f/CC);
        const float var = sq * (1.0f/CC) - m*m;
        const float inv = rsqrtf(var + 1e-5f);
        const size_t row = (size_t)n * HW + i0 + r;
        #pragma unroll
        for (int t = 0; t < 4; ++t) {
            const int c = lane + t*32;
            const float v = tile[r][c];
            xt[row*CC + c] = v;
            xn[row*CC + c] = (v - m) * inv * g[c] + b[c];
        }
    }
}

// ---------------------------------------------------------------------------
// Generic tiled fp32 GEMM:  C = epilogue(A[MxK] @ B[KxN] + bias)
// BM=BN=128, BK=16, 256 threads, 8x8 per-thread micro-tile.
// EPI 0: (acc+bias)*alpha   EPI 1: acc+bias+res   EPI 2: gelu(acc+bias)
// ---------------------------------------------------------------------------
template<int EPI>
__global__ __launch_bounds__(256, 2)
void gemm_kernel(const float* __restrict__ A, const float* __restrict__ B,
                 const float* __restrict__ bias, const float* __restrict__ res,
                 float* __restrict__ C, int M, int N, int K, float alpha)
{
    __shared__ __align__(16) float As[16][128];
    __shared__ __align__(16) float Bs[16][128];

    const int tid = threadIdx.x;
    const int tx = tid & 15, ty = tid >> 4;
    const int m0 = blockIdx.y * 128, n0 = blockIdx.x * 128;

    const int arow = tid >> 1;          // 0..127
    const int acol = (tid & 1) * 8;     // 0 or 8
    const int brow = tid >> 5;          // 0..7
    const int bcol = (tid & 31) * 4;

    float acc[8][8];
    #pragma unroll
    for (int i = 0; i < 8; ++i)
        #pragma unroll
        for (int j = 0; j < 8; ++j) acc[i][j] = 0.f;

    const float* Aptr = A + (size_t)(m0 + arow) * K + acol;
    const float* Bptr = B + (size_t)brow * N + n0 + bcol;

    for (int k0 = 0; k0 < K; k0 += 16) {
        const float4 a0 = *(const float4*)(Aptr + k0);
        const float4 a1 = *(const float4*)(Aptr + k0 + 4);
        *(float4*)&Bs[brow    ][bcol] = *(const float4*)(Bptr + (size_t) k0      * N);
        *(float4*)&Bs[brow + 8][bcol] = *(const float4*)(Bptr + (size_t)(k0 + 8) * N);
        As[acol+0][arow] = a0.x; As[acol+1][arow] = a0.y;
        As[acol+2][arow] = a0.z; As[acol+3][arow] = a0.w;
        As[acol+4][arow] = a1.x; As[acol+5][arow] = a1.y;
        As[acol+6][arow] = a1.z; As[acol+7][arow] = a1.w;
        __syncthreads();

        #pragma unroll
        for (int kk = 0; kk < 16; ++kk) {
            const float4 a0v = *(const float4*)&As[kk][ty*8];
            const float4 a1v = *(const float4*)&As[kk][ty*8 + 4];
            const float4 b0v = *(const float4*)&Bs[kk][tx*8];
            const float4 b1v = *(const float4*)&Bs[kk][tx*8 + 4];
            const float av[8] = {a0v.x,a0v.y,a0v.z,a0v.w,a1v.x,a1v.y,a1v.z,a1v.w};
            const float bv[8] = {b0v.x,b0v.y,b0v.z,b0v.w,b1v.x,b1v.y,b1v.z,b1v.w};
            #pragma unroll
            for (int i = 0; i < 8; ++i)
                #pragma unroll
                for (int j = 0; j < 8; ++j) acc[i][j] += av[i] * bv[j];
        }
        __syncthreads();
    }

    float bvals[8];
    #pragma unroll
    for (int j = 0; j < 8; ++j) bvals[j] = bias[n0 + tx*8 + j];

    #pragma unroll
    for (int i = 0; i < 8; ++i) {
        const size_t m = (size_t)m0 + ty*8 + i;
        float vals[8];
        if constexpr (EPI == 1) {
            const float4 r0 = *(const float4*)&res[m*N + n0 + tx*8];
            const float4 r1 = *(const float4*)&res[m*N + n0 + tx*8 + 4];
            const float rv[8] = {r0.x,r0.y,r0.z,r0.w,r1.x,r1.y,r1.z,r1.w};
            #pragma unroll
            for (int j = 0; j < 8; ++j) vals[j] = acc[i][j] + bvals[j] + rv[j];
        } else if constexpr (EPI == 2) {
            #pragma unroll
            for (int j = 0; j < 8; ++j) vals[j] = gelu_f(acc[i][j] + bvals[j]);
        } else {
            #pragma unroll
            for (int j = 0; j < 8; ++j) vals[j] = (acc[i][j] + bvals[j]) * alpha;
        }
        *(float4*)&C[m*N + n0 + tx*8    ] = make_float4(vals[0], vals[1], vals[2], vals[3]);
        *(float4*)&C[m*N + n0 + tx*8 + 4] = make_float4(vals[4], vals[5], vals[6], vals[7]);
    }
}

// ---------------------------------------------------------------------------
// Kernel 3: indexed epipolar attention.  One block (128 thr) per query row.
// ---------------------------------------------------------------------------
__global__ __launch_bounds__(128)
void attn_kernel(const float* __restrict__ q, const float* __restrict__ k,
                 const float* __restrict__ v, const int* __restrict__ widx,
                 const float* __restrict__ dp,
                 const float* __restrict__ kpe, const float* __restrict__ vpe,
                 const float* __restrict__ rpe, float* __restrict__ out)
{
    const int r = blockIdx.x;
    const int n = r >> 12;
    const int pairbase = (n ^ 1) * HW;     // v=2 view swap
    const int tid = threadIdx.x, lane = tid & 31, wp = tid >> 5;

    __shared__ __align__(16) float Qs[CC];
    __shared__ float attn_s[DD];
    __shared__ float cost_s[DD];
    __shared__ int   idx_s[DD];
    __shared__ float red[4];

    const float qv = q[(size_t)r*CC + tid];
    Qs[tid] = qv;
    const float ws = warp_sum(qv);
    if (lane == 0) red[wp] = ws;
    if (tid < DD) idx_s[tid] = widx[(size_t)r*DD + tid];
    __syncthreads();
    const float qsum = red[0] + red[1] + red[2] + red[3];

    // Phase 1: cost[k] = Q . K[pair, idx[k]]   (warp w handles k in [16w,16w+16))
    const float4 myq = ((const float4*)Qs)[lane];
    float part[16];
    #pragma unroll
    for (int t = 0; t < 16; ++t) {
        const int kk = wp*16 + t;
        const float4 kv = ((const float4*)(k + ((size_t)(pairbase + idx_s[kk]))*CC))[lane];
        part[t] = myq.x*kv.x + myq.y*kv.y + myq.z*kv.z + myq.w*kv.w;
    }
    #pragma unroll
    for (int t = 0; t < 16; ++t) {
        const int kk = wp*16 + t;
        const float d = warp_sum(part[t]);
        if (lane == 0) cost_s[kk] = d + qsum * kpe[kk] + rpe[kk];
    }
    __syncthreads();

    // Phase 2: softmax -> * depth_prob -> eps-renorm  (warp 0, 2 k per lane)
    if (wp == 0) {
        const float c0 = cost_s[lane], c1 = cost_s[lane + 32];
        const float m  = warp_max(fmaxf(c0, c1));
        const float e0 = __expf(c0 - m), e1 = __expf(c1 - m);
        const float se = warp_sum(e0 + e1);
        const float is = 1.0f / se;
        const float t0 = e0 * is * dp[(size_t)r*DD + lane];
        const float t1 = e1 * is * dp[(size_t)r*DD + lane + 32];
        const float st = warp_sum(t0 + t1);
        const float dn = 1.0f / (st + 1e-10f);
        const float a0 = (t0 + 1e-10f) * dn;
        const float a1 = (t1 + 1e-10f) * dn;
        attn_s[lane] = a0; attn_s[lane + 32] = a1;
        const float pe = warp_sum(a0 * vpe[lane] + a1 * vpe[lane + 32]);
        if (lane == 0) red[0] = pe;
    }
    __syncthreads();

    // Phase 3: out[c] = pe + sum_k attn[k] * V[pair, idx[k], c]
    float a0 = red[0], a1 = 0.f, a2 = 0.f, a3 = 0.f;
    #pragma unroll 4
    for (int kk = 0; kk < DD; kk += 4) {
        a0 += attn_s[kk+0] * v[((size_t)(pairbase + idx_s[kk+0]))*CC + tid];
        a1 += attn_s[kk+1] * v[((size_t)(pairbase + idx_s[kk+1]))*CC + tid];
        a2 += attn_s[kk+2] * v[((size_t)(pairbase + idx_s[kk+2]))*CC + tid];
        a3 += attn_s[kk+3] * v[((size_t)(pairbase + idx_s[kk+3]))*CC + tid];
    }
    out[(size_t)r*CC + tid] = (a0 + a1) + (a2 + a3);
}

// ---------------------------------------------------------------------------
// Kernel 4: row LayerNorm (c=128) for LN2
// ---------------------------------------------------------------------------
__global__ __launch_bounds__(128)
void ln_kernel(const float* __restrict__ x, const float* __restrict__ g,
               const float* __restrict__ b, float* __restrict__ o)
{
    const int row = blockIdx.x, tid = threadIdx.x, lane = tid & 31, wp = tid >> 5;
    __shared__ float rs[4], rq[4];
    const float v = x[(size_t)row*CC + tid];
    const float s  = warp_sum(v);
    const float sq = warp_sum(v * v);
    if (lane == 0) { rs[wp] = s; rq[wp] = sq; }
    __syncthreads();
    const float S  = rs[0] + rs[1] + rs[2] + rs[3];
    const float SQ = rq[0] + rq[1] + rq[2] + rq[3];
    const float m   = S * (1.0f/CC);
    const float var = SQ * (1.0f/CC) - m*m;
    o[(size_t)row*CC + tid] = (v - m) * rsqrtf(var + 1e-5f) * g[tid] + b[tid];
}

// ---------------------------------------------------------------------------
// Kernel 5: depthwise 5x5 conv (SAME) + gelu + add.  Channel-parallel threads.
// ---------------------------------------------------------------------------
__global__ __launch_bounds__(256)
void dwconv_kernel(const float* __restrict__ y, const float* __restrict__ wgt,
                   const float* __restrict__ bias, float* __restrict__ yt)
{
    const int hc = threadIdx.x;                 // 0..255
    const int n = blockIdx.z, hh = blockIdx.y, w0 = blockIdx.x * 8;
    float wr[25];
    #pragma unroll
    for (int t = 0; t < 25; ++t) wr[t] = wgt[hc*25 + t];
    const float bb = bias[hc];
    const float* yb  = y  + (size_t)n * HW * HIDN;
    float*       ytb = yt + (size_t)n * HW * HIDN;

    #pragma unroll
    for (int j = 0; j < 8; ++j) {
        const int ww = w0 + j;
        float acc = 0.f;
        #pragma unroll
        for (int kh = 0; kh < 5; ++kh) {
            const int yy = hh + kh - 2;
            if ((unsigned)yy >= (unsigned)HH) continue;
            #pragma unroll
            for (int kw = 0; kw < 5; ++kw) {
                const int xx = ww + kw - 2;
                if ((unsigned)xx >= (unsigned)WW) continue;
                acc += wr[kh*5 + kw] * yb[(size_t)(yy*WW + xx) * HIDN + hc];
            }
        }
        const int pix = hh*WW + ww;
        const float base = yb[(size_t)pix * HIDN + hc];
        ytb[(size_t)pix * HIDN + hc] = base + gelu_f(acc + bb);
    }
}

// ---------------------------------------------------------------------------
extern "C" void kernel_launch(void* const* d_in, const int* in_sizes, int n_in,
                              void* d_out, int out_size)
{
    const float* feat   = (const float*)d_in[0];
    const int*   widx   = (const int*)  d_in[1];
    const float* dp     = (const float*)d_in[2];
    const float* ln1_g  = (const float*)d_in[3];
    const float* ln1_b  = (const float*)d_in[4];
    const float* wq     = (const float*)d_in[5];
    const float* bq     = (const float*)d_in[6];
    const float* wk     = (const float*)d_in[7];
    const float* bk     = (const float*)d_in[8];
    const float* wv     = (const float*)d_in[9];
    const float* bv     = (const float*)d_in[10];
    const float* kpe    = (const float*)d_in[11];
    const float* vpe    = (const float*)d_in[12];
    const float* rpe    = (const float*)d_in[13];
    const float* proj_w = (const float*)d_in[14];
    const float* proj_b = (const float*)d_in[15];
    const float* ln2_g  = (const float*)d_in[16];
    const float* ln2_b  = (const float*)d_in[17];
    const float* fc1_w  = (const float*)d_in[18];
    const float* fc1_b  = (const float*)d_in[19];
    const float* dw_w   = (const float*)d_in[20];
    const float* dw_b   = (const float*)d_in[21];
    const float* fc2_w  = (const float*)d_in[22];
    const float* fc2_b  = (const float*)d_in[23];

    float *xt, *xn, *q, *k, *v, *ao, *x2, *xn2, *y, *yt;
    cudaGetSymbolAddress((void**)&xt,  g_xt);
    cudaGetSymbolAddress((void**)&xn,  g_xn);
    cudaGetSymbolAddress((void**)&q,   g_q);
    cudaGetSymbolAddress((void**)&k,   g_k);
    cudaGetSymbolAddress((void**)&v,   g_v);
    cudaGetSymbolAddress((void**)&ao,  g_ao);
    cudaGetSymbolAddress((void**)&x2,  g_x2);
    cudaGetSymbolAddress((void**)&xn2, g_xn2);
    cudaGetSymbolAddress((void**)&y,   g_y);
    cudaGetSymbolAddress((void**)&yt,  g_yt);

    const float scale = 0.08838834764831845f;   // 128^-0.5

    // 1. transpose + LN1
    transpose_ln1_kernel<<<dim3(HW/32, BB), 256>>>(feat, ln1_g, ln1_b, xt, xn);

    // 2. QKV projections (Q pre-scaled)
    gemm_kernel<0><<<dim3(1, ROWS/128), 256>>>(xn, wq, bq, nullptr, q, ROWS, CC, CC, scale);
    gemm_kernel<0><<<dim3(1, ROWS/128), 256>>>(xn, wk, bk, nullptr, k, ROWS, CC, CC, 1.0f);
    gemm_kernel<0><<<dim3(1, ROWS/128), 256>>>(xn, wv, bv, nullptr, v, ROWS, CC, CC, 1.0f);

    // 3. indexed attention
    attn_kernel<<<ROWS, 128>>>(q, k, v, widx, dp, kpe, vpe, rpe, ao);

    // 4. proj + residual (shortcut = x_t)
    gemm_kernel<1><<<dim3(1, ROWS/128), 256>>>(ao, proj_w, proj_b, xt, x2, ROWS, CC, CC, 1.0f);

    // 5. LN2
    ln_kernel<<<ROWS, 128>>>(x2, ln2_g, ln2_b, xn2);

    // 6. fc1 + gelu
    gemm_kernel<2><<<dim3(2, ROWS/128), 256>>>(xn2, fc1_w, fc1_b, nullptr, y, ROWS, HIDN, CC, 1.0f);

    // 7. depthwise conv + gelu + add
    dwconv_kernel<<<dim3(WW/8, HH, BB), 256>>>(y, dw_w, dw_b, yt);

    // 8. fc2 + residual (x2) -> final output
    gemm_kernel<1><<<dim3(1, ROWS/128), 256>>>(yt, fc2_w, fc2_b, x2, (float*)d_out, ROWS, CC, HIDN, 1.0f);
}

// round 13
// speedup vs baseline: 1.0053x; 1.0053x over previous
#include <cuda_runtime.h>
#include <math.h>
#include <stdint.h>

// Problem constants (fixed by setup_inputs)
#define BB      4        // b*v
#define HW      4096
#define CC      128
#define DD      64
#define HIDN    256
#define HH      64
#define WW      64
#define ROWS    (BB*HW)  // 16384

__device__ float g_xt [ROWS*CC];
__device__ float g_xn [ROWS*CC];
__device__ float g_q  [ROWS*CC];
__device__ float g_k  [ROWS*CC];
__device__ float g_v  [ROWS*CC];
__device__ float g_ao [ROWS*CC];
__device__ float g_x2 [ROWS*CC];
__device__ float g_xn2[ROWS*CC];
__device__ float g_y  [ROWS*HIDN];
__device__ float g_yt [ROWS*HIDN];

__device__ __forceinline__ float warp_sum(float v) {
    #pragma unroll
    for (int o = 16; o > 0; o >>= 1) v += __shfl_xor_sync(0xffffffffu, v, o);
    return v;
}
__device__ __forceinline__ float warp_max(float v) {
    #pragma unroll
    for (int o = 16; o > 0; o >>= 1) v = fmaxf(v, __shfl_xor_sync(0xffffffffu, v, o));
    return v;
}
__device__ __forceinline__ float gelu_f(float x) {
    return 0.5f * x * (1.0f + erff(x * 0.7071067811865475f));
}

// ---------------------------------------------------------------------------
// Kernel 1: transpose (B,C,HW)->(B,HW,C) + LayerNorm1.  Writes x_t and xn.
// ---------------------------------------------------------------------------
__global__ __launch_bounds__(256)
void transpose_ln1_kernel(const float* __restrict__ feat,
                          const float* __restrict__ g, const float* __restrict__ b,
                          float* __restrict__ xt, float* __restrict__ xn)
{
    __shared__ float tile[32][129];
    const int n  = blockIdx.y;
    const int i0 = blockIdx.x * 32;
    const int tid = threadIdx.x, lane = tid & 31, wp = tid >> 5;

    const float* fptr = feat + (size_t)n * CC * HW;
    #pragma unroll
    for (int c = wp; c < CC; c += 8)
        tile[lane][c] = fptr[(size_t)c * HW + i0 + lane];
    __syncthreads();

    #pragma unroll
    for (int qq = 0; qq < 4; ++qq) {
        const int r = wp * 4 + qq;
        float s = 0.f, sq = 0.f;
        #pragma unroll
        for (int t = 0; t < 4; ++t) { float v = tile[r][lane + t*32]; s += v; sq += v*v; }
        s  = warp_sum(s);
        sq = warp_sum(sq);
        const float m   = s * (1.0f/CC);
        const float var = sq * (1.0f/CC) - m*m;
        const float inv = rsqrtf(var + 1e-5f);
        const size_t row = (size_t)n * HW + i0 + r;
        #pragma unroll
        for (int t = 0; t < 4; ++t) {
            const int c = lane + t*32;
            const float v = tile[r][c];
            xt[row*CC + c] = v;
            xn[row*CC + c] = (v - m) * inv * g[c] + b[c];
        }
    }
}

// ---------------------------------------------------------------------------
// Generic tiled fp32 GEMM:  C = epilogue(A[MxK] @ B[KxN] + bias)
// BM=BN=128, BK=16, 256 threads, 8x8 per-thread micro-tile.
// EPI 0: (acc+bias)*alpha   EPI 1: acc+bias+res   EPI 2: gelu(acc+bias)
// ---------------------------------------------------------------------------
template<int EPI>
__global__ __launch_bounds__(256, 2)
void gemm_kernel(const float* __restrict__ A, const float* __restrict__ B,
                 const float* __restrict__ bias, const float* __restrict__ res,
                 float* __restrict__ C, int M, int N, int K, float alpha)
{
    __shared__ __align__(16) float As[16][128];
    __shared__ __align__(16) float Bs[16][128];

    const int tid = threadIdx.x;
    const int tx = tid & 15, ty = tid >> 4;
    const int m0 = blockIdx.y * 128, n0 = blockIdx.x * 128;

    const int arow = tid >> 1;          // 0..127
    const int acol = (tid & 1) * 8;     // 0 or 8
    const int brow = tid >> 5;          // 0..7
    const int bcol = (tid & 31) * 4;

    float acc[8][8];
    #pragma unroll
    for (int i = 0; i < 8; ++i)
        #pragma unroll
        for (int j = 0; j < 8; ++j) acc[i][j] = 0.f;

    const float* Aptr = A + (size_t)(m0 + arow) * K + acol;
    const float* Bptr = B + (size_t)brow * N + n0 + bcol;

    for (int k0 = 0; k0 < K; k0 += 16) {
        const float4 a0 = *(const float4*)(Aptr + k0);
        const float4 a1 = *(const float4*)(Aptr + k0 + 4);
        *(float4*)&Bs[brow    ][bcol] = *(const float4*)(Bptr + (size_t) k0      * N);
        *(float4*)&Bs[brow + 8][bcol] = *(const float4*)(Bptr + (size_t)(k0 + 8) * N);
        As[acol+0][arow] = a0.x; As[acol+1][arow] = a0.y;
        As[acol+2][arow] = a0.z; As[acol+3][arow] = a0.w;
        As[acol+4][arow] = a1.x; As[acol+5][arow] = a1.y;
        As[acol+6][arow] = a1.z; As[acol+7][arow] = a1.w;
        __syncthreads();

        #pragma unroll
        for (int kk = 0; kk < 16; ++kk) {
            const float4 a0v = *(const float4*)&As[kk][ty*8];
            const float4 a1v = *(const float4*)&As[kk][ty*8 + 4];
            const float4 b0v = *(const float4*)&Bs[kk][tx*8];
            const float4 b1v = *(const float4*)&Bs[kk][tx*8 + 4];
            const float av[8] = {a0v.x,a0v.y,a0v.z,a0v.w,a1v.x,a1v.y,a1v.z,a1v.w};
            const float bv[8] = {b0v.x,b0v.y,b0v.z,b0v.w,b1v.x,b1v.y,b1v.z,b1v.w};
            #pragma unroll
            for (int i = 0; i < 8; ++i)
                #pragma unroll
                for (int j = 0; j < 8; ++j) acc[i][j] += av[i] * bv[j];
        }
        __syncthreads();
    }

    float bvals[8];
    #pragma unroll
    for (int j = 0; j < 8; ++j) bvals[j] = bias[n0 + tx*8 + j];

    #pragma unroll
    for (int i = 0; i < 8; ++i) {
        const size_t m = (size_t)m0 + ty*8 + i;
        float vals[8];
        if constexpr (EPI == 1) {
            const float4 r0 = *(const float4*)&res[m*N + n0 + tx*8];
            const float4 r1 = *(const float4*)&res[m*N + n0 + tx*8 + 4];
            const float rv[8] = {r0.x,r0.y,r0.z,r0.w,r1.x,r1.y,r1.z,r1.w};
            #pragma unroll
            for (int j = 0; j < 8; ++j) vals[j] = acc[i][j] + bvals[j] + rv[j];
        } else if constexpr (EPI == 2) {
            #pragma unroll
            for (int j = 0; j < 8; ++j) vals[j] = gelu_f(acc[i][j] + bvals[j]);
        } else {
            #pragma unroll
            for (int j = 0; j < 8; ++j) vals[j] = (acc[i][j] + bvals[j]) * alpha;
        }
        *(float4*)&C[m*N + n0 + tx*8    ] = make_float4(vals[0], vals[1], vals[2], vals[3]);
        *(float4*)&C[m*N + n0 + tx*8 + 4] = make_float4(vals[4], vals[5], vals[6], vals[7]);
    }
}

// ---------------------------------------------------------------------------
// Kernel 3: indexed epipolar attention.  One block (128 thr) per query row.
// ---------------------------------------------------------------------------
__global__ __launch_bounds__(128)
void attn_kernel(const float* __restrict__ q, const float* __restrict__ k,
                 const float* __restrict__ v, const int* __restrict__ widx,
                 const float* __restrict__ dp,
                 const float* __restrict__ kpe, const float* __restrict__ vpe,
                 const float* __restrict__ rpe, float* __restrict__ out)
{
    const int r = blockIdx.x;
    const int n = r >> 12;
    const int pairbase = (n ^ 1) * HW;     // v=2 view swap
    const int tid = threadIdx.x, lane = tid & 31, wp = tid >> 5;

    __shared__ __align__(16) float Qs[CC];
    __shared__ float attn_s[DD];
    __shared__ float cost_s[DD];
    __shared__ int   idx_s[DD];
    __shared__ float red[4];

    const float qv = q[(size_t)r*CC + tid];
    Qs[tid] = qv;
    const float ws = warp_sum(qv);
    if (lane == 0) red[wp] = ws;
    if (tid < DD) idx_s[tid] = widx[(size_t)r*DD + tid];
    __syncthreads();
    const float qsum = red[0] + red[1] + red[2] + red[3];

    // Phase 1: cost[k] = Q . K[pair, idx[k]]   (warp w handles k in [16w,16w+16))
    const float4 myq = ((const float4*)Qs)[lane];
    float part[16];
    #pragma unroll
    for (int t = 0; t < 16; ++t) {
        const int kk = wp*16 + t;
        const float4 kv = ((const float4*)(k + ((size_t)(pairbase + idx_s[kk]))*CC))[lane];
        part[t] = myq.x*kv.x + myq.y*kv.y + myq.z*kv.z + myq.w*kv.w;
    }
    #pragma unroll
    for (int t = 0; t < 16; ++t) {
        const int kk = wp*16 + t;
        const float d = warp_sum(part[t]);
        if (lane == 0) cost_s[kk] = d + qsum * kpe[kk] + rpe[kk];
    }
    __syncthreads();

    // Phase 2: softmax -> * depth_prob -> eps-renorm  (warp 0, 2 k per lane)
    if (wp == 0) {
        const float c0 = cost_s[lane], c1 = cost_s[lane + 32];
        const float m  = warp_max(fmaxf(c0, c1));
        const float e0 = __expf(c0 - m), e1 = __expf(c1 - m);
        const float se = warp_sum(e0 + e1);
        const float is = 1.0f / se;
        const float t0 = e0 * is * dp[(size_t)r*DD + lane];
        const float t1 = e1 * is * dp[(size_t)r*DD + lane + 32];
        const float st = warp_sum(t0 + t1);
        const float dn = 1.0f / (st + 1e-10f);
        const float a0 = (t0 + 1e-10f) * dn;
        const float a1 = (t1 + 1e-10f) * dn;
        attn_s[lane] = a0; attn_s[lane + 32] = a1;
        const float pe = warp_sum(a0 * vpe[lane] + a1 * vpe[lane + 32]);
        if (lane == 0) red[0] = pe;
    }
    __syncthreads();

    // Phase 3: out[c] = pe + sum_k attn[k] * V[pair, idx[k], c]
    float a0 = red[0], a1 = 0.f, a2 = 0.f, a3 = 0.f;
    #pragma unroll 4
    for (int kk = 0; kk < DD; kk += 4) {
        a0 += attn_s[kk+0] * v[((size_t)(pairbase + idx_s[kk+0]))*CC + tid];
        a1 += attn_s[kk+1] * v[((size_t)(pairbase + idx_s[kk+1]))*CC + tid];
        a2 += attn_s[kk+2] * v[((size_t)(pairbase + idx_s[kk+2]))*CC + tid];
        a3 += attn_s[kk+3] * v[((size_t)(pairbase + idx_s[kk+3]))*CC + tid];
    }
    out[(size_t)r*CC + tid] = (a0 + a1) + (a2 + a3);
}

// ---------------------------------------------------------------------------
// Kernel 4: row LayerNorm (c=128) for LN2
// ---------------------------------------------------------------------------
__global__ __launch_bounds__(128)
void ln_kernel(const float* __restrict__ x, const float* __restrict__ g,
               const float* __restrict__ b, float* __restrict__ o)
{
    const int row = blockIdx.x, tid = threadIdx.x, lane = tid & 31, wp = tid >> 5;
    __shared__ float rs[4], rq[4];
    const float v = x[(size_t)row*CC + tid];
    const float s  = warp_sum(v);
    const float sq = warp_sum(v * v);
    if (lane == 0) { rs[wp] = s; rq[wp] = sq; }
    __syncthreads();
    const float S  = rs[0] + rs[1] + rs[2] + rs[3];
    const float SQ = rq[0] + rq[1] + rq[2] + rq[3];
    const float m   = S * (1.0f/CC);
    const float var = SQ * (1.0f/CC) - m*m;
    o[(size_t)row*CC + tid] = (v - m) * rsqrtf(var + 1e-5f) * g[tid] + b[tid];
}

// ---------------------------------------------------------------------------
// Kernel 5: depthwise 5x5 conv (SAME) + gelu + add.  Channel-parallel threads.
// ---------------------------------------------------------------------------
__global__ __launch_bounds__(256)
void dwconv_kernel(const float* __restrict__ y, const float* __restrict__ wgt,
                   const float* __restrict__ bias, float* __restrict__ yt)
{
    const int hc = threadIdx.x;                 // 0..255
    const int n = blockIdx.z, hh = blockIdx.y, w0 = blockIdx.x * 8;
    float wr[25];
    #pragma unroll
    for (int t = 0; t < 25; ++t) wr[t] = wgt[hc*25 + t];
    const float bb = bias[hc];
    const float* yb  = y  + (size_t)n * HW * HIDN;
    float*       ytb = yt + (size_t)n * HW * HIDN;

    #pragma unroll
    for (int j = 0; j < 8; ++j) {
        const int ww = w0 + j;
        float acc = 0.f;
        #pragma unroll
        for (int kh = 0; kh < 5; ++kh) {
            const int yy = hh + kh - 2;
            if ((unsigned)yy >= (unsigned)HH) continue;
            #pragma unroll
            for (int kw = 0; kw < 5; ++kw) {
                const int xx = ww + kw - 2;
                if ((unsigned)xx >= (unsigned)WW) continue;
                acc += wr[kh*5 + kw] * yb[(size_t)(yy*WW + xx) * HIDN + hc];
            }
        }
        const int pix = hh*WW + ww;
        const float base = yb[(size_t)pix * HIDN + hc];
        ytb[(size_t)pix * HIDN + hc] = base + gelu_f(acc + bb);
    }
}

// ---------------------------------------------------------------------------
extern "C" void kernel_launch(void* const* d_in, const int* in_sizes, int n_in,
                              void* d_out, int out_size)
{
    const float* feat   = (const float*)d_in[0];
    const int*   widx   = (const int*)  d_in[1];
    const float* dp     = (const float*)d_in[2];
    const float* ln1_g  = (const float*)d_in[3];
    const float* ln1_b  = (const float*)d_in[4];
    const float* wq     = (const float*)d_in[5];
    const float* bq     = (const float*)d_in[6];
    const float* wk     = (const float*)d_in[7];
    const float* bk     = (const float*)d_in[8];
    const float* wv     = (const float*)d_in[9];
    const float* bv     = (const float*)d_in[10];
    const float* kpe    = (const float*)d_in[11];
    const float* vpe    = (const float*)d_in[12];
    const float* rpe    = (const float*)d_in[13];
    const float* proj_w = (const float*)d_in[14];
    const float* proj_b = (const float*)d_in[15];
    const float* ln2_g  = (const float*)d_in[16];
    const float* ln2_b  = (const float*)d_in[17];
    const float* fc1_w  = (const float*)d_in[18];
    const float* fc1_b  = (const float*)d_in[19];
    const float* dw_w   = (const float*)d_in[20];
    const float* dw_b   = (const float*)d_in[21];
    const float* fc2_w  = (const float*)d_in[22];
    const float* fc2_b  = (const float*)d_in[23];

    float *xt, *xn, *q, *k, *v, *ao, *x2, *xn2, *y, *yt;
    cudaGetSymbolAddress((void**)&xt,  g_xt);
    cudaGetSymbolAddress((void**)&xn,  g_xn);
    cudaGetSymbolAddress((void**)&q,   g_q);
    cudaGetSymbolAddress((void**)&k,   g_k);
    cudaGetSymbolAddress((void**)&v,   g_v);
    cudaGetSymbolAddress((void**)&ao,  g_ao);
    cudaGetSymbolAddress((void**)&x2,  g_x2);
    cudaGetSymbolAddress((void**)&xn2, g_xn2);
    cudaGetSymbolAddress((void**)&y,   g_y);
    cudaGetSymbolAddress((void**)&yt,  g_yt);

    const float scale = 0.08838834764831845f;   // 128^-0.5

    // 1. transpose + LN1
    transpose_ln1_kernel<<<dim3(HW/32, BB), 256>>>(feat, ln1_g, ln1_b, xt, xn);

    // 2. QKV projections (Q pre-scaled)
    gemm_kernel<0><<<dim3(1, ROWS/128), 256>>>(xn, wq, bq, nullptr, q, ROWS, CC, CC, scale);
    gemm_kernel<0><<<dim3(1, ROWS/128), 256>>>(xn, wk, bk, nullptr, k, ROWS, CC, CC, 1.0f);
    gemm_kernel<0><<<dim3(1, ROWS/128), 256>>>(xn, wv, bv, nullptr, v, ROWS, CC, CC, 1.0f);

    // 3. indexed attention
    attn_kernel<<<ROWS, 128>>>(q, k, v, widx, dp, kpe, vpe, rpe, ao);

    // 4. proj + residual (shortcut = x_t)
    gemm_kernel<1><<<dim3(1, ROWS/128), 256>>>(ao, proj_w, proj_b, xt, x2, ROWS, CC, CC, 1.0f);

    // 5. LN2
    ln_kernel<<<ROWS, 128>>>(x2, ln2_g, ln2_b, xn2);

    // 6. fc1 + gelu
    gemm_kernel<2><<<dim3(2, ROWS/128), 256>>>(xn2, fc1_w, fc1_b, nullptr, y, ROWS, HIDN, CC, 1.0f);

    // 7. depthwise conv + gelu + add
    dwconv_kernel<<<dim3(WW/8, HH, BB), 256>>>(y, dw_w, dw_b, yt);

    // 8. fc2 + residual (x2) -> final output
    gemm_kernel<1><<<dim3(1, ROWS/128), 256>>>(yt, fc2_w, fc2_b, x2, (float*)d_out, ROWS, CC, HIDN, 1.0f);
}